// round 8
// baseline (speedup 1.0000x reference)
#include <cuda_runtime.h>
#include <cstdint>

#define PVOL   29791
#define MROWS  119164
#define D1     512
#define KK     128
#define BM     128
#define BN     64
#define NCOL   8
#define NT     256

// smem float offsets
#define F_AHI   0                    // 128*128
#define F_ALO   16384
#define F_BHI   32768                // 64*128
#define F_BLO   40960
#define F_YSQP  49152                // 2*128
#define F_WSQP  49408                // 4*64
#define F_YSQ   49664                // 128
#define F_WSQ   49792                // 64
#define SMEM_FLOATS 49856            // 199,424 bytes

// conflict-free smem indexing (XOR swizzle on k by low row bits)
__device__ __forceinline__ int idxA(int m, int k) { return m * 128 + (k ^ ((m & 7) << 2)); }
__device__ __forceinline__ int idxB(int n, int k) { return n * 128 + (k ^ ((n & 7) << 2)); }
__device__ __forceinline__ int idxS(int c, int m) { return c * 128 + (m ^ ((c & 7) << 2)); }

__device__ __forceinline__ uint32_t tf32of(float v) {
    uint32_t r;
    asm("cvt.rna.tf32.f32 %0, %1;" : "=r"(r) : "f"(v));
    return r;
}

__device__ __forceinline__ void mma_tf32(float* d, const uint32_t* a, const uint32_t* b) {
    asm volatile(
        "mma.sync.aligned.m16n8k8.row.col.f32.tf32.tf32.f32 "
        "{%0,%1,%2,%3}, {%4,%5,%6,%7}, {%8,%9}, {%0,%1,%2,%3};"
        : "+f"(d[0]), "+f"(d[1]), "+f"(d[2]), "+f"(d[3])
        : "r"(a[0]), "r"(a[1]), "r"(a[2]), "r"(a[3]), "r"(b[0]), "r"(b[1]));
}

__global__ __launch_bounds__(NT, 1)
void gk_kernel(const float* __restrict__ x, const float* __restrict__ w,
               float* __restrict__ out) {
    extern __shared__ float sm[];
    uint32_t* sAhi = (uint32_t*)(sm + F_AHI);
    uint32_t* sAlo = (uint32_t*)(sm + F_ALO);
    uint32_t* sBhi = (uint32_t*)(sm + F_BHI);
    uint32_t* sBlo = (uint32_t*)(sm + F_BLO);
    float*    st   = sm + F_BHI;          // stage reuses Bhi after mma
    float*    ysqp = sm + F_YSQP;
    float*    wsqp = sm + F_WSQP;
    float*    ysq  = sm + F_YSQ;
    float*    wsq  = sm + F_WSQ;

    const int tid  = threadIdx.x;
    const int wid  = tid >> 5;
    const int lane = tid & 31;
    const int row0 = blockIdx.x * BM;

    // ---------------- gather A -> hi/lo tf32 (swizzled) + ||y||^2 -----------
    {
        const int m    = tid & 127;
        const int half = tid >> 7;            // kw bit
        const int row  = row0 + m;
        float s = 0.0f;
        if (row < MROWS) {
            const int n   = row / PVOL;
            const int p   = row - n * PVOL;
            const int d   = p / 961;
            const int rem = p - d * 961;
            const int h   = rem / 31;
            const int wx  = rem - h * 31;
            const long base = (long)n * 524288 + d * 1024 + h * 32 + wx + half;
            #pragma unroll 4
            for (int it = 0; it < 64; ++it) {
                const int c  = it >> 2;
                const int kd = (it >> 1) & 1;
                const int kh = it & 1;
                const int k  = c * 8 + kd * 4 + kh * 2 + half;
                const float v = x[base + (long)c * 32768 + kd * 1024 + kh * 32];
                const uint32_t hib = tf32of(v);
                const float lo = v - __uint_as_float(hib);
                const int o = idxA(m, k);
                sAhi[o] = hib;
                sAlo[o] = tf32of(lo);
                s = fmaf(v, v, s);
            }
        } else {
            #pragma unroll 4
            for (int it = 0; it < 64; ++it) {
                const int k = (it >> 2) * 8 + (((it >> 1) & 1) << 2) + ((it & 1) << 1) + half;
                const int o = idxA(m, k);
                sAhi[o] = 0u;
                sAlo[o] = 0u;
            }
        }
        ysqp[half * 128 + m] = s;
    }
    __syncthreads();
    if (tid < 128) ysq[tid] = ysqp[tid] + ysqp[128 + tid];

    // per-warp frag coordinates
    const int c  = lane & 3;
    const int rg = lane >> 2;
    const int m0 = (wid & 3) * 32;
    const int n0 = (wid >> 2) * 32;

    for (int iter = 0; iter < NCOL; ++iter) {
        const int col0 = iter * BN;

        // ------------- fill B hi/lo + ||w||^2 -------------------------------
        {
            const int nn = tid & 63;
            const int qk = tid >> 6;
            float s = 0.0f;
            const float* wr = w + (long)(col0 + nn) * KK + qk * 32;
            #pragma unroll
            for (int i = 0; i < 8; ++i) {
                const float4 v4 = *(const float4*)(wr + i * 4);
                const float vv[4] = {v4.x, v4.y, v4.z, v4.w};
                #pragma unroll
                for (int e = 0; e < 4; ++e) {
                    const int k = qk * 32 + i * 4 + e;
                    const float v = vv[e];
                    const uint32_t hib = tf32of(v);
                    const float lo = v - __uint_as_float(hib);
                    const int o = idxB(nn, k);
                    sBhi[o] = hib;
                    sBlo[o] = tf32of(lo);
                    s = fmaf(v, v, s);
                }
            }
            wsqp[qk * 64 + nn] = s;
        }
        __syncthreads();
        if (tid < 64)
            wsq[tid] = (wsqp[tid] + wsqp[64 + tid]) + (wsqp[128 + tid] + wsqp[192 + tid]);
        __syncthreads();

        // ------------- tensor-core GEMM (3-pass tf32 split) ------------------
        float acc[2][4][4];
        #pragma unroll
        for (int f = 0; f < 2; ++f)
            #pragma unroll
            for (int g = 0; g < 4; ++g)
                #pragma unroll
                for (int e = 0; e < 4; ++e) acc[f][g][e] = 0.0f;

        #pragma unroll 4
        for (int ks = 0; ks < 16; ++ks) {
            const int kb = ks * 8;
            uint32_t ahi[2][4], alo[2][4], bhi[4][2], blo[4][2];
            #pragma unroll
            for (int f = 0; f < 2; ++f) {
                const int r = m0 + f * 16 + rg;
                const int o0 = idxA(r,     kb + c);
                const int o1 = idxA(r + 8, kb + c);
                const int o2 = idxA(r,     kb + c + 4);
                const int o3 = idxA(r + 8, kb + c + 4);
                ahi[f][0] = sAhi[o0]; ahi[f][1] = sAhi[o1];
                ahi[f][2] = sAhi[o2]; ahi[f][3] = sAhi[o3];
                alo[f][0] = sAlo[o0]; alo[f][1] = sAlo[o1];
                alo[f][2] = sAlo[o2]; alo[f][3] = sAlo[o3];
            }
            #pragma unroll
            for (int g = 0; g < 4; ++g) {
                const int n = n0 + g * 8 + rg;
                const int o0 = idxB(n, kb + c);
                const int o1 = idxB(n, kb + c + 4);
                bhi[g][0] = sBhi[o0]; bhi[g][1] = sBhi[o1];
                blo[g][0] = sBlo[o0]; blo[g][1] = sBlo[o1];
            }
            // pass 1: hi*hi — 8 independent accumulators
            #pragma unroll
            for (int f = 0; f < 2; ++f)
                #pragma unroll
                for (int g = 0; g < 4; ++g) mma_tf32(acc[f][g], ahi[f], bhi[g]);
            // pass 2: hi*lo
            #pragma unroll
            for (int f = 0; f < 2; ++f)
                #pragma unroll
                for (int g = 0; g < 4; ++g) mma_tf32(acc[f][g], ahi[f], blo[g]);
            // pass 3: lo*hi
            #pragma unroll
            for (int f = 0; f < 2; ++f)
                #pragma unroll
                for (int g = 0; g < 4; ++g) mma_tf32(acc[f][g], alo[f], bhi[g]);
        }
        __syncthreads();   // done reading sBhi/sBlo; stage may overwrite Bhi

        // ------------- epilogue: exp -> swizzled stage -----------------------
        #pragma unroll
        for (int f = 0; f < 2; ++f) {
            const int r0 = m0 + f * 16 + rg;
            const int r1 = r0 + 8;
            const float ys0 = ysq[r0];
            const float ys1 = ysq[r1];
            #pragma unroll
            for (int g = 0; g < 4; ++g) {
                const int cb = n0 + g * 8 + 2 * c;
                const float ws0 = wsq[cb];
                const float ws1 = wsq[cb + 1];
                st[idxS(cb,     r0)] = __expf(fmaf(2.0f, acc[f][g][0], -(ys0 + ws0)));
                st[idxS(cb + 1, r0)] = __expf(fmaf(2.0f, acc[f][g][1], -(ys0 + ws1)));
                st[idxS(cb,     r1)] = __expf(fmaf(2.0f, acc[f][g][2], -(ys1 + ws0)));
                st[idxS(cb + 1, r1)] = __expf(fmaf(2.0f, acc[f][g][3], -(ys1 + ws1)));
            }
        }
        __syncthreads();

        // ------------- coalesced global stores -------------------------------
        #pragma unroll 4
        for (int l = 0; l < 32; ++l) {
            const int e   = tid + l * NT;
            const int col = e >> 7;            // 0..63
            const int m   = e & 127;
            const int row = row0 + m;
            if (row < MROWS) {
                const int n = row / PVOL;
                const int p = row - n * PVOL;
                out[(long)(n * D1 + col0 + col) * PVOL + p] = st[idxS(col, m)];
            }
        }
        __syncthreads();   // protect Bhi(stage)/Blo before next fill
    }
}

extern "C" void kernel_launch(void* const* d_in, const int* in_sizes, int n_in,
                              void* d_out, int out_size) {
    const float* x = (const float*)d_in[0];
    const float* w = (const float*)d_in[1];
    float* out = (float*)d_out;

    const int smem_bytes = SMEM_FLOATS * (int)sizeof(float);  // 199,424
    cudaFuncSetAttribute(gk_kernel, cudaFuncAttributeMaxDynamicSharedMemorySize,
                         smem_bytes);
    dim3 grid((MROWS + BM - 1) / BM, 1);   // 931
    gk_kernel<<<grid, NT, smem_bytes>>>(x, w, out);
}

// round 9
// speedup vs baseline: 1.0623x; 1.0623x over previous
#include <cuda_runtime.h>
#include <cstdint>

#define PVOL   29791
#define MROWS  119164
#define D1     512
#define KK     128
#define BM     128
#define BN     64
#define NCOL   8
#define NT     512

// smem float offsets
#define F_AHI   0                    // 128*128
#define F_ALO   16384
#define F_BHI   32768                // 64*128
#define F_BLO   40960
#define F_YSQP  49152                // 4*128
#define F_WSQP  49664                // 8*64
#define F_YSQ   50176                // 128
#define F_WSQ   50304                // 64
#define SMEM_FLOATS 50368            // 201,472 bytes

// swizzled indices (XOR on k, 16B granular) — used by scalar fills
__device__ __forceinline__ int idxA(int m, int k) { return m * 128 + (k ^ ((m & 7) << 2)); }
__device__ __forceinline__ int idxB(int n, int k) { return n * 128 + (k ^ ((n & 7) << 2)); }
__device__ __forceinline__ int idxS(int c, int m) { return c * 128 + (m ^ ((c & 7) << 2)); }

__device__ __forceinline__ uint32_t s2u(const void* p) {
    uint32_t a;
    asm("{ .reg .u64 t; cvta.to.shared.u64 t, %1; cvt.u32.u64 %0, t; }" : "=r"(a) : "l"(p));
    return a;
}
__device__ __forceinline__ uint32_t tf32of(float v) {
    uint32_t r;
    asm("cvt.rna.tf32.f32 %0, %1;" : "=r"(r) : "f"(v));
    return r;
}
__device__ __forceinline__ void ldsm4(uint32_t& r0, uint32_t& r1, uint32_t& r2, uint32_t& r3,
                                      uint32_t addr) {
    asm volatile("ldmatrix.sync.aligned.m8n8.x4.shared.b16 {%0,%1,%2,%3}, [%4];"
                 : "=r"(r0), "=r"(r1), "=r"(r2), "=r"(r3) : "r"(addr));
}
__device__ __forceinline__ void mma_tf32(float* d, const uint32_t* a, uint32_t b0, uint32_t b1) {
    asm volatile(
        "mma.sync.aligned.m16n8k8.row.col.f32.tf32.tf32.f32 "
        "{%0,%1,%2,%3}, {%4,%5,%6,%7}, {%8,%9}, {%0,%1,%2,%3};"
        : "+f"(d[0]), "+f"(d[1]), "+f"(d[2]), "+f"(d[3])
        : "r"(a[0]), "r"(a[1]), "r"(a[2]), "r"(a[3]), "r"(b0), "r"(b1));
}

__global__ __launch_bounds__(NT, 1)
void gk_kernel(const float* __restrict__ x, const float* __restrict__ w,
               float* __restrict__ out) {
    extern __shared__ float sm[];
    uint32_t* sAhi = (uint32_t*)(sm + F_AHI);
    uint32_t* sAlo = (uint32_t*)(sm + F_ALO);
    uint32_t* sBhi = (uint32_t*)(sm + F_BHI);
    uint32_t* sBlo = (uint32_t*)(sm + F_BLO);
    float*    st   = sm + F_BHI;          // stage reuses Bhi after mma reads
    float*    ysqp = sm + F_YSQP;
    float*    wsqp = sm + F_WSQP;
    float*    ysq  = sm + F_YSQ;
    float*    wsq  = sm + F_WSQ;

    const uint32_t aAhi = s2u(sAhi);
    const uint32_t aAlo = s2u(sAlo);
    const uint32_t aBhi = s2u(sBhi);
    const uint32_t aBlo = s2u(sBlo);

    const int tid  = threadIdx.x;
    const int wid  = tid >> 5;
    const int lane = tid & 31;
    const int row0 = blockIdx.x * BM;

    // ---------------- gather A -> hi/lo tf32 (swizzled) + ||y||^2 -----------
    {
        const int m   = tid & 127;
        const int khw = tid >> 7;            // 0..3 = (kh,kw)
        const int row = row0 + m;
        float s = 0.0f;
        if (row < MROWS) {
            const int n   = row / PVOL;
            const int p   = row - n * PVOL;
            const int d   = p / 961;
            const int rem = p - d * 961;
            const int h   = rem / 31;
            const int wx  = rem - h * 31;
            const int kh  = khw >> 1;
            const int kw  = khw & 1;
            const long base = (long)n * 524288 + d * 1024 + h * 32 + wx + kh * 32 + kw;
            #pragma unroll 4
            for (int it = 0; it < 32; ++it) {
                const int c  = it >> 1;
                const int kd = it & 1;
                const int k  = c * 8 + kd * 4 + khw;
                const float v = x[base + (long)c * 32768 + kd * 1024];
                const uint32_t hib = tf32of(v);
                const float lo = v - __uint_as_float(hib);
                const int o = idxA(m, k);
                sAhi[o] = hib;
                sAlo[o] = tf32of(lo);
                s = fmaf(v, v, s);
            }
        } else {
            #pragma unroll 4
            for (int it = 0; it < 32; ++it) {
                const int k = (it >> 1) * 8 + (it & 1) * 4 + khw;
                const int o = idxA(m, k);
                sAhi[o] = 0u;
                sAlo[o] = 0u;
            }
        }
        ysqp[khw * 128 + m] = s;
    }
    __syncthreads();
    if (tid < 128)
        ysq[tid] = (ysqp[tid] + ysqp[128 + tid]) + (ysqp[256 + tid] + ysqp[384 + tid]);

    // ---- per-warp fragment geometry ----
    const int m0 = (wid & 3) * 32;       // warp M origin (4 warps over 128)
    const int n0 = (wid >> 2) * 16;      // warp N origin (4 warps over 64)
    const int r    = lane & 7;
    const int midx = lane >> 3;
    const int kh4  = (midx >> 1) * 4;    // k-half in k-units
    const int xorv = r << 2;             // swizzle XOR in k-units
    // ldmatrix row bases (bytes): row * 128 floats * 4
    const uint32_t rowA0 = (uint32_t)(m0 + (midx & 1) * 8 + r) * 512u;
    const uint32_t rowA1 = rowA0 + 16u * 512u;
    const uint32_t rowB  = (uint32_t)(n0 + (midx & 1) * 8 + r) * 512u;

    const int c  = lane & 3;             // for epilogue/acc mapping
    const int rg = lane >> 2;

    for (int iter = 0; iter < NCOL; ++iter) {
        const int col0 = iter * BN;

        // ------------- fill B hi/lo + ||w||^2 -------------------------------
        {
            const int nn = tid & 63;
            const int qk = tid >> 6;          // 0..7 -> 16 k's
            float s = 0.0f;
            const float* wr = w + (long)(col0 + nn) * KK + qk * 16;
            #pragma unroll
            for (int i = 0; i < 4; ++i) {
                const float4 v4 = *(const float4*)(wr + i * 4);
                const float vv[4] = {v4.x, v4.y, v4.z, v4.w};
                #pragma unroll
                for (int e = 0; e < 4; ++e) {
                    const int k = qk * 16 + i * 4 + e;
                    const float v = vv[e];
                    const uint32_t hib = tf32of(v);
                    const float lo = v - __uint_as_float(hib);
                    const int o = idxB(nn, k);
                    sBhi[o] = hib;
                    sBlo[o] = tf32of(lo);
                    s = fmaf(v, v, s);
                }
            }
            wsqp[qk * 64 + nn] = s;
        }
        __syncthreads();
        if (tid < 64) {
            float s = 0.0f;
            #pragma unroll
            for (int q = 0; q < 8; ++q) s += wsqp[q * 64 + tid];
            wsq[tid] = s;
        }
        __syncthreads();

        // ------------- tensor GEMM: 3-pass tf32, ldmatrix-fed ---------------
        float acc[2][2][4];
        #pragma unroll
        for (int f = 0; f < 2; ++f)
            #pragma unroll
            for (int g = 0; g < 2; ++g)
                #pragma unroll
                for (int e = 0; e < 4; ++e) acc[f][g][e] = 0.0f;

        #pragma unroll 4
        for (int ks = 0; ks < 16; ++ks) {
            const uint32_t ka = (uint32_t)((((ks * 8) | kh4) ^ xorv) << 2);
            uint32_t ahi[2][4], alo[2][4], bh[4], bl[4];
            ldsm4(ahi[0][0], ahi[0][1], ahi[0][2], ahi[0][3], aAhi + rowA0 + ka);
            ldsm4(ahi[1][0], ahi[1][1], ahi[1][2], ahi[1][3], aAhi + rowA1 + ka);
            ldsm4(alo[0][0], alo[0][1], alo[0][2], alo[0][3], aAlo + rowA0 + ka);
            ldsm4(alo[1][0], alo[1][1], alo[1][2], alo[1][3], aAlo + rowA1 + ka);
            ldsm4(bh[0], bh[1], bh[2], bh[3], aBhi + rowB + ka);
            ldsm4(bl[0], bl[1], bl[2], bl[3], aBlo + rowB + ka);

            #pragma unroll
            for (int f = 0; f < 2; ++f)
                #pragma unroll
                for (int g = 0; g < 2; ++g) {
                    mma_tf32(acc[f][g], ahi[f], bh[g], bh[2 + g]);   // hi*hi
                    mma_tf32(acc[f][g], ahi[f], bl[g], bl[2 + g]);   // hi*lo
                    mma_tf32(acc[f][g], alo[f], bh[g], bh[2 + g]);   // lo*hi
                }
        }
        __syncthreads();   // done reading sBhi/sBlo; stage overwrites Bhi

        // ------------- epilogue: exp -> swizzled stage -----------------------
        #pragma unroll
        for (int f = 0; f < 2; ++f) {
            const int r0 = m0 + f * 16 + rg;
            const int r1 = r0 + 8;
            const float ys0 = ysq[r0];
            const float ys1 = ysq[r1];
            #pragma unroll
            for (int g = 0; g < 2; ++g) {
                const int cb = n0 + g * 8 + 2 * c;
                const float ws0 = wsq[cb];
                const float ws1 = wsq[cb + 1];
                st[idxS(cb,     r0)] = __expf(fmaf(2.0f, acc[f][g][0], -(ys0 + ws0)));
                st[idxS(cb + 1, r0)] = __expf(fmaf(2.0f, acc[f][g][1], -(ys0 + ws1)));
                st[idxS(cb,     r1)] = __expf(fmaf(2.0f, acc[f][g][2], -(ys1 + ws0)));
                st[idxS(cb + 1, r1)] = __expf(fmaf(2.0f, acc[f][g][3], -(ys1 + ws1)));
            }
        }
        __syncthreads();

        // ------------- coalesced global stores -------------------------------
        #pragma unroll 4
        for (int l = 0; l < 16; ++l) {
            const int e   = tid + l * NT;
            const int col = e >> 7;            // 0..63
            const int m   = e & 127;
            const int row = row0 + m;
            if (row < MROWS) {
                const int n = row / PVOL;
                const int p = row - n * PVOL;
                out[(long)(n * D1 + col0 + col) * PVOL + p] = st[idxS(col, m)];
            }
        }
        __syncthreads();   // protect Bhi(stage)/Blo before next fill
    }
}

extern "C" void kernel_launch(void* const* d_in, const int* in_sizes, int n_in,
                              void* d_out, int out_size) {
    const float* x = (const float*)d_in[0];
    const float* w = (const float*)d_in[1];
    float* out = (float*)d_out;

    const int smem_bytes = SMEM_FLOATS * (int)sizeof(float);  // 201,472
    cudaFuncSetAttribute(gk_kernel, cudaFuncAttributeMaxDynamicSharedMemorySize,
                         smem_bytes);
    dim3 grid((MROWS + BM - 1) / BM, 1);   // 931
    gk_kernel<<<grid, NT, smem_bytes>>>(x, w, out);
}

// round 10
// speedup vs baseline: 1.1250x; 1.0591x over previous
#include <cuda_runtime.h>
#include <cstdint>

#define PVOL   29791
#define MROWS  119164
#define D1     512
#define KK     128
#define BM     128
#define BN     64
#define NCOL   8
#define NT     512

// smem float offsets
#define F_AHI   0                    // 128*128
#define F_ALO   16384
#define F_BHI   32768                // 64*128
#define F_BLO   40960
#define F_YSQP  49152                // 4*128
#define F_YSQ   49664                // 128
#define F_WSQ   49792                // 64
#define SMEM_FLOATS 49856            // 199,424 bytes

__device__ __forceinline__ int idxA(int m, int k) { return m * 128 + (k ^ ((m & 7) << 2)); }
__device__ __forceinline__ int idxB(int n, int k) { return n * 128 + (k ^ ((n & 7) << 2)); }
__device__ __forceinline__ int idxS(int c, int m) { return c * 128 + (m ^ ((c & 7) << 2)); }

__device__ __forceinline__ uint32_t s2u(const void* p) {
    uint32_t a;
    asm("{ .reg .u64 t; cvta.to.shared.u64 t, %1; cvt.u32.u64 %0, t; }" : "=r"(a) : "l"(p));
    return a;
}
__device__ __forceinline__ uint32_t tf32of(float v) {
    uint32_t r;
    asm("cvt.rna.tf32.f32 %0, %1;" : "=r"(r) : "f"(v));
    return r;
}
__device__ __forceinline__ void ldsm4(uint32_t& r0, uint32_t& r1, uint32_t& r2, uint32_t& r3,
                                      uint32_t addr) {
    asm volatile("ldmatrix.sync.aligned.m8n8.x4.shared.b16 {%0,%1,%2,%3}, [%4];"
                 : "=r"(r0), "=r"(r1), "=r"(r2), "=r"(r3) : "r"(addr));
}
__device__ __forceinline__ void mma_tf32(float* d, const uint32_t* a, uint32_t b0, uint32_t b1) {
    asm volatile(
        "mma.sync.aligned.m16n8k8.row.col.f32.tf32.tf32.f32 "
        "{%0,%1,%2,%3}, {%4,%5,%6,%7}, {%8,%9}, {%0,%1,%2,%3};"
        : "+f"(d[0]), "+f"(d[1]), "+f"(d[2]), "+f"(d[3])
        : "r"(a[0]), "r"(a[1]), "r"(a[2]), "r"(a[3]), "r"(b0), "r"(b1));
}

#define LOAD_FRAGS(KS, AH, AL, BH, BL) do {                                    \
    const uint32_t ka_ = (uint32_t)(((((KS) * 8) | kh4) ^ xorv) << 2);         \
    ldsm4(AH[0][0], AH[0][1], AH[0][2], AH[0][3], aAhi + rowA0 + ka_);         \
    ldsm4(AH[1][0], AH[1][1], AH[1][2], AH[1][3], aAhi + rowA1 + ka_);         \
    ldsm4(AL[0][0], AL[0][1], AL[0][2], AL[0][3], aAlo + rowA0 + ka_);         \
    ldsm4(AL[1][0], AL[1][1], AL[1][2], AL[1][3], aAlo + rowA1 + ka_);         \
    ldsm4(BH[0], BH[1], BH[2], BH[3], aBhi + rowB + ka_);                      \
    ldsm4(BL[0], BL[1], BL[2], BL[3], aBlo + rowB + ka_);                      \
} while (0)

#define DO_MMAS(AH, AL, BH, BL) do {                                           \
    _Pragma("unroll")                                                          \
    for (int f_ = 0; f_ < 2; ++f_) {                                           \
        _Pragma("unroll")                                                      \
        for (int g_ = 0; g_ < 2; ++g_) {                                       \
            mma_tf32(acc[f_][g_], AH[f_], BH[g_], BH[2 + g_]);                 \
            mma_tf32(acc[f_][g_], AH[f_], BL[g_], BL[2 + g_]);                 \
            mma_tf32(acc[f_][g_], AL[f_], BH[g_], BH[2 + g_]);                 \
        }                                                                      \
    }                                                                          \
} while (0)

__global__ __launch_bounds__(NT, 1)
void gk_kernel(const float* __restrict__ x, const float* __restrict__ w,
               float* __restrict__ out) {
    extern __shared__ float sm[];
    uint32_t* sAhi = (uint32_t*)(sm + F_AHI);
    uint32_t* sAlo = (uint32_t*)(sm + F_ALO);
    uint32_t* sBhi = (uint32_t*)(sm + F_BHI);
    uint32_t* sBlo = (uint32_t*)(sm + F_BLO);
    float*    st   = sm + F_BHI;          // stage reuses Bhi after mma reads
    float*    ysqp = sm + F_YSQP;
    float*    ysq  = sm + F_YSQ;
    float*    wsq  = sm + F_WSQ;

    const uint32_t aAhi = s2u(sAhi);
    const uint32_t aAlo = s2u(sAlo);
    const uint32_t aBhi = s2u(sBhi);
    const uint32_t aBlo = s2u(sBlo);

    const int tid  = threadIdx.x;
    const int wid  = tid >> 5;
    const int lane = tid & 31;
    const int row0 = blockIdx.x * BM;

    // ---------------- gather A -> hi/lo tf32 (swizzled) + ||y||^2 -----------
    {
        const int m   = tid & 127;
        const int khw = tid >> 7;            // 0..3 = (kh,kw)
        const int row = row0 + m;
        float s = 0.0f;
        if (row < MROWS) {
            const int n   = row / PVOL;
            const int p   = row - n * PVOL;
            const int d   = p / 961;
            const int rem = p - d * 961;
            const int h   = rem / 31;
            const int wx  = rem - h * 31;
            const int kh  = khw >> 1;
            const int kw  = khw & 1;
            const long base = (long)n * 524288 + d * 1024 + h * 32 + wx + kh * 32 + kw;
            #pragma unroll 4
            for (int it = 0; it < 32; ++it) {
                const int c  = it >> 1;
                const int kd = it & 1;
                const int k  = c * 8 + kd * 4 + khw;
                const float v = x[base + (long)c * 32768 + kd * 1024];
                const uint32_t hib = tf32of(v);
                const float lo = v - __uint_as_float(hib);
                const int o = idxA(m, k);
                sAhi[o] = hib;
                sAlo[o] = tf32of(lo);
                s = fmaf(v, v, s);
            }
        } else {
            #pragma unroll 4
            for (int it = 0; it < 32; ++it) {
                const int k = (it >> 1) * 8 + (it & 1) * 4 + khw;
                const int o = idxA(m, k);
                sAhi[o] = 0u;
                sAlo[o] = 0u;
            }
        }
        ysqp[khw * 128 + m] = s;
    }
    __syncthreads();
    if (tid < 128)
        ysq[tid] = (ysqp[tid] + ysqp[128 + tid]) + (ysqp[256 + tid] + ysqp[384 + tid]);

    // ---- per-warp fragment geometry ----
    const int m0 = (wid & 3) * 32;
    const int n0 = (wid >> 2) * 16;
    const int r    = lane & 7;
    const int midx = lane >> 3;
    const int kh4  = (midx >> 1) * 4;
    const int xorv = r << 2;
    const uint32_t rowA0 = (uint32_t)(m0 + (midx & 1) * 8 + r) * 512u;
    const uint32_t rowA1 = rowA0 + 16u * 512u;
    const uint32_t rowB  = (uint32_t)(n0 + (midx & 1) * 8 + r) * 512u;

    const int c  = lane & 3;
    const int rg = lane >> 2;

    for (int iter = 0; iter < NCOL; ++iter) {
        const int col0 = iter * BN;

        // ------------- fill B hi/lo (STS.128) + ||w||^2 via shfl ------------
        {
            const int cg  = lane >> 3;          // 0..3 -> column within warp
            const int sub = lane & 7;           // 16-k chunk
            const int nn  = wid * 4 + cg;       // 0..63 local column
            const float* wr = w + (long)(col0 + nn) * KK + sub * 16;
            float s = 0.0f;
            #pragma unroll
            for (int j = 0; j < 4; ++j) {
                const float4 v4 = *(const float4*)(wr + j * 4);
                uint4 h4, l4;
                h4.x = tf32of(v4.x); l4.x = tf32of(v4.x - __uint_as_float(h4.x));
                h4.y = tf32of(v4.y); l4.y = tf32of(v4.y - __uint_as_float(h4.y));
                h4.z = tf32of(v4.z); l4.z = tf32of(v4.z - __uint_as_float(h4.z));
                h4.w = tf32of(v4.w); l4.w = tf32of(v4.w - __uint_as_float(h4.w));
                const int o = idxB(nn, sub * 16 + j * 4);
                *(uint4*)&sBhi[o] = h4;
                *(uint4*)&sBlo[o] = l4;
                s = fmaf(v4.x, v4.x, s);
                s = fmaf(v4.y, v4.y, s);
                s = fmaf(v4.z, v4.z, s);
                s = fmaf(v4.w, v4.w, s);
            }
            s += __shfl_xor_sync(0xFFFFFFFFu, s, 4);
            s += __shfl_xor_sync(0xFFFFFFFFu, s, 2);
            s += __shfl_xor_sync(0xFFFFFFFFu, s, 1);
            if (sub == 0) wsq[nn] = s;
        }
        __syncthreads();

        // ------------- tensor GEMM: 3-pass tf32, prefetched fragments --------
        float acc[2][2][4];
        #pragma unroll
        for (int f = 0; f < 2; ++f)
            #pragma unroll
            for (int g = 0; g < 2; ++g)
                #pragma unroll
                for (int e = 0; e < 4; ++e) acc[f][g][e] = 0.0f;

        uint32_t ah0[2][4], al0[2][4], bh0[4], bl0[4];
        uint32_t ah1[2][4], al1[2][4], bh1[4], bl1[4];
        LOAD_FRAGS(0, ah0, al0, bh0, bl0);
        #pragma unroll
        for (int ks = 0; ks < 16; ++ks) {
            if ((ks & 1) == 0) {
                if (ks < 15) LOAD_FRAGS(ks + 1, ah1, al1, bh1, bl1);
                DO_MMAS(ah0, al0, bh0, bl0);
            } else {
                if (ks < 15) LOAD_FRAGS(ks + 1, ah0, al0, bh0, bl0);
                DO_MMAS(ah1, al1, bh1, bl1);
            }
        }
        __syncthreads();   // done reading sBhi/sBlo; stage overwrites Bhi

        // ------------- epilogue: exp -> swizzled stage -----------------------
        #pragma unroll
        for (int f = 0; f < 2; ++f) {
            const int r0 = m0 + f * 16 + rg;
            const int r1 = r0 + 8;
            const float ys0 = ysq[r0];
            const float ys1 = ysq[r1];
            #pragma unroll
            for (int g = 0; g < 2; ++g) {
                const int cb = n0 + g * 8 + 2 * c;
                const float ws0 = wsq[cb];
                const float ws1 = wsq[cb + 1];
                st[idxS(cb,     r0)] = __expf(fmaf(2.0f, acc[f][g][0], -(ys0 + ws0)));
                st[idxS(cb + 1, r0)] = __expf(fmaf(2.0f, acc[f][g][1], -(ys0 + ws1)));
                st[idxS(cb,     r1)] = __expf(fmaf(2.0f, acc[f][g][2], -(ys1 + ws0)));
                st[idxS(cb + 1, r1)] = __expf(fmaf(2.0f, acc[f][g][3], -(ys1 + ws1)));
            }
        }
        __syncthreads();

        // ------------- coalesced global stores -------------------------------
        #pragma unroll 4
        for (int l = 0; l < 16; ++l) {
            const int e   = tid + l * NT;
            const int col = e >> 7;            // 0..63
            const int m   = e & 127;
            const int row = row0 + m;
            if (row < MROWS) {
                const int n = row / PVOL;
                const int p = row - n * PVOL;
                out[(long)(n * D1 + col0 + col) * PVOL + p] = st[idxS(col, m)];
            }
        }
        __syncthreads();   // protect Bhi(stage)/Blo before next fill
    }
}

extern "C" void kernel_launch(void* const* d_in, const int* in_sizes, int n_in,
                              void* d_out, int out_size) {
    const float* x = (const float*)d_in[0];
    const float* w = (const float*)d_in[1];
    float* out = (float*)d_out;

    const int smem_bytes = SMEM_FLOATS * (int)sizeof(float);  // 199,424
    cudaFuncSetAttribute(gk_kernel, cudaFuncAttributeMaxDynamicSharedMemorySize,
                         smem_bytes);
    dim3 grid((MROWS + BM - 1) / BM, 1);   // 931
    gk_kernel<<<grid, NT, smem_bytes>>>(x, w, out);
}